// round 5
// baseline (speedup 1.0000x reference)
#include <cuda_runtime.h>
#include <math.h>

// ---------------------------------------------------------------------------
// LocalPseudoFeatLoss: B=2, C=19, H=W=128, CH=64, K=7, TOPK=8
// ---------------------------------------------------------------------------

namespace {
constexpr int NC   = 19;
constexpr int NCP  = 20;     // padded classes
constexpr int HH   = 128;
constexpr int WW   = 128;
constexpr int HWp  = HH * WW;
constexpr int FC   = 64;
constexpr int KK   = 7;
constexpr int K2   = KK * KK;
constexpr int NTOP = 9;
constexpr int NBOT = 8;
constexpr int NPIX = 2 * HWp;
constexpr float EPSV = 1e-8f;
constexpr int FB = FC * 4;    // feature row bytes
constexpr int PB = NCP * 4;   // prob row bytes
}

__device__ float  g_x[NPIX * FC];      // PRE-NORMALIZED features (src, then ema)
__device__ float  g_pp[NPIX * NCP];    // softmax(logits), pixel-major, padded
__device__ double g_acc[8];
// 0 sum_src_pos 1 cnt_src_pos 2 sum_src_neg 3 cnt_src_neg
// 4 sum_sim_pos 5 sum_sim_neg 6 cnt_trg

__device__ __forceinline__ float dot4(float4 a, float4 b) {
    float d = a.x * b.x;
    d = fmaf(a.y, b.y, d);
    d = fmaf(a.z, b.z, d);
    d = fmaf(a.w, b.w, d);
    return d;
}

// Reduce 8 values across 16 lanes (segmented exchange tree).
// On return, lanes {2n, 2n+1} both hold total of value n.
__device__ __forceinline__ float tree8(float v[8], unsigned mask, int lane) {
    {   bool hi = (lane & 8) != 0;
        #pragma unroll
        for (int j = 0; j < 4; j++) {
            float mine = hi ? v[j] : v[j + 4];
            float kept = hi ? v[j + 4] : v[j];
            v[j] = kept + __shfl_xor_sync(mask, mine, 8);
        } }
    {   bool hi = (lane & 4) != 0;
        #pragma unroll
        for (int j = 0; j < 2; j++) {
            float mine = hi ? v[j] : v[j + 2];
            float kept = hi ? v[j + 2] : v[j];
            v[j] = kept + __shfl_xor_sync(mask, mine, 4);
        } }
    {   bool hi = (lane & 2) != 0;
        float mine = hi ? v[0] : v[1];
        float kept = hi ? v[1] : v[0];
        v[0] = kept + __shfl_xor_sync(mask, mine, 2);
    }
    v[0] += __shfl_xor_sync(mask, v[0], 1);
    return v[0];
}

// transpose [C][HW] -> [pix][C], PRE-NORMALIZED by 1/max(||x||,eps)
__global__ void __launch_bounds__(256)
k_tr(const float* __restrict__ src) {
    __shared__ float sm[FC][33];
    int pix0 = blockIdx.x * 32;
    int b   = pix0 / HWp;
    int hw0 = pix0 - b * HWp;
    int t = threadIdx.x;

    int px = t & 31, cb = (t >> 5) * 8;
    const float* sp = src + (size_t)b * FC * HWp + hw0 + px;
    #pragma unroll
    for (int j = 0; j < 8; j++)
        sm[cb + j][px] = sp[(size_t)(cb + j) * HWp];
    __syncthreads();

    int px2 = t >> 3, part = t & 7;
    float v[8];
    float ss = 0.f;
    #pragma unroll
    for (int j = 0; j < 8; j++) {
        v[j] = sm[part * 8 + j][px2];
        ss = fmaf(v[j], v[j], ss);
    }
    #pragma unroll
    for (int o = 4; o; o >>= 1) ss += __shfl_xor_sync(0xffffffffu, ss, o);
    float rn = 1.f / fmaxf(sqrtf(ss), EPSV);
    float4* d = reinterpret_cast<float4*>(g_x + (size_t)(pix0 + px2) * FC + part * 8);
    d[0] = make_float4(v[0] * rn, v[1] * rn, v[2] * rn, v[3] * rn);
    d[1] = make_float4(v[4] * rn, v[5] * rn, v[6] * rn, v[7] * rn);
}

// softmax per pixel -> pixel-major padded (+ zero the accumulators)
__global__ void __launch_bounds__(256)
k_soft(const float* __restrict__ logits) {
    if (blockIdx.x == 0 && threadIdx.x < 8) g_acc[threadIdx.x] = 0.0;
    int pix = blockIdx.x * blockDim.x + threadIdx.x;
    if (pix >= NPIX) return;
    int b  = pix / HWp;
    int hw = pix - b * HWp;
    const float* lb = logits + (size_t)b * NC * HWp + hw;
    float l[NC];
    float mx = -3.4e38f;
    #pragma unroll
    for (int c = 0; c < NC; c++) {
        l[c] = lb[(size_t)c * HWp];
        mx = fmaxf(mx, l[c]);
    }
    float s = 0.f;
    #pragma unroll
    for (int c = 0; c < NC; c++) { l[c] = expf(l[c] - mx); s += l[c]; }
    float inv = 1.f / s;
    #pragma unroll
    for (int c = 0; c < NC; c++) g_pp[(size_t)pix * NCP + c] = l[c] * inv;
    g_pp[(size_t)pix * NCP + NC] = 0.f;
}

// ---- source loss: 16 lanes/pixel, deferred reduce, interior fast path ----
__global__ void __launch_bounds__(512)
k_src(const int* __restrict__ gt) {
    int bx = blockIdx.x;
    int b  = bx >> 9;
    int tt = bx & 511;
    int h0 = (tt >> 4) << 2;     // 32 h-tiles of 4
    int w0 = (tt & 15) << 3;     // 16 w-tiles of 8
    int g    = threadIdx.x >> 4;
    int lane = threadIdx.x & 15;
    unsigned gmask = 0xFFFFu << (threadIdx.x & 16);
    int h = h0 + (g >> 3), w = w0 + (g & 7);
    int pix = b * HWp + h * WW + w;

    bool interior = (h0 >= 4) && (h0 <= 120) && (w0 >= 8) && (w0 <= 112);

    float sp = 0.f, sn = 0.f;
    float cp = 0.f, cn = 0.f;
    int gc = gt[pix];
    if (gc != 255) {
        const char* Pl = (const char*)g_x + (size_t)pix * FB + lane * 16;
        float4 f = *(const float4*)Pl;
        if (interior) {
            float tot = 0.f, spp = 0.f;
            int cpp = 0;
            #pragma unroll 1
            for (int ky = 0; ky < KK; ky++) {
                const char* Pr = Pl + (ptrdiff_t)(ky - 3) * (WW * FB);
                const int* Pg = gt + pix + (ky - 3) * WW;
                #pragma unroll
                for (int kx = 0; kx < KK; kx++) {
                    float4 nf = *(const float4*)(Pr + (kx - 3) * FB);
                    float s = dot4(f, nf);
                    int gn = Pg[kx - 3];
                    tot += s;
                    if (gn == gc) { spp += s; cpp++; }
                }
            }
            sp = spp; sn = tot - spp;
            cp = (float)cpp; cn = (float)(K2 - cpp);
        } else {
            int cpp = 0, cnn = 0;
            #pragma unroll 1
            for (int ky = 0; ky < KK; ky++) {
                int hn = h + ky - 3;
                bool rv = (unsigned)hn < (unsigned)HH;
                int hc = min(max(hn, 0), HH - 1);
                #pragma unroll
                for (int kx = 0; kx < KK; kx++) {
                    int wn = w + kx - 3;
                    bool ok = rv && ((unsigned)wn < (unsigned)WW);
                    int wc = min(max(wn, 0), WW - 1);
                    int pn = b * HWp + hc * WW + wc;
                    float4 nf = *(const float4*)((const char*)g_x + (size_t)pn * FB + lane * 16);
                    float s = dot4(f, nf);
                    int gn = gt[pn];
                    if (!ok) { s = 0.f; gn = 0; }
                    if (gn == gc) { sp += s; cpp++; }
                    else          { sn += s; cnn++; }
                }
            }
            cp = (float)cpp; cn = (float)cnn;
        }
        #pragma unroll
        for (int o = 8; o; o >>= 1) {
            sp += __shfl_xor_sync(gmask, sp, o);
            sn += __shfl_xor_sync(gmask, sn, o);
        }
    }
    __shared__ float sa[4];
    if (threadIdx.x < 4) sa[threadIdx.x] = 0.f;
    __syncthreads();
    if (gc != 255 && lane == 0) {
        atomicAdd(&sa[0], sp);
        atomicAdd(&sa[1], cp);
        atomicAdd(&sa[2], sn);
        atomicAdd(&sa[3], cn);
    }
    __syncthreads();
    if (threadIdx.x == 0) {
        atomicAdd(&g_acc[0], (double)sa[0]);
        atomicAdd(&g_acc[1], (double)sa[1]);
        atomicAdd(&g_acc[2], (double)sa[2]);
        atomicAdd(&g_acc[3], (double)sa[3]);
    }
}

// ---- target: 64-thread blocks, tile 8x4 = 32 px.
//      phase 1: 4 groups x 16 lanes, 8 px per group (R4 chunk/tree8 code)
//      phase 2: 64 threads = 32 px x {top, bottom} -> full utilization ----
__global__ void __launch_bounds__(64)
k_trg(const float* __restrict__ mix) {
    __shared__ float sm_s[K2][33];   // [33]: conflict-free chunk writes
    __shared__ float sm_c[K2][33];
    __shared__ float red[6];

    int bx = blockIdx.x;             // 1024 blocks
    int b  = bx >> 9;
    int tt = bx & 511;               // 16 x 32 tiles of 8x4
    int h0 = (tt >> 5) << 3;
    int w0 = (tt & 31) << 2;
    int g    = threadIdx.x >> 4;     // 0..3 : column in tile
    int lane = threadIdx.x & 15;
    unsigned gmask = 0xFFFFu << (threadIdx.x & 16);
    int w = w0 + g;

    bool gInt = (h0 >= 8) && (h0 <= 112) && (w >= 3) && (w <= 124);

    // ---- phase 1: each group computes 8 pixels' 49 sims + cross-probs ----
    #pragma unroll 1
    for (int i = 0; i < 8; i++) {
        int h = h0 + i;
        int pix = b * HWp + h * WW + w;
        int q = i * 4 + g;           // pixel slot in tile
        if (!((1.f - mix[pix]) > 0.5f)) continue;

        const char* Pl  = (const char*)g_x  + (size_t)pix * FB + lane * 16;
        const char* Ppl = (const char*)g_pp + (size_t)pix * PB + lane * 16;
        float4 f  = *(const float4*)Pl;
        float4 pc = (lane < 5) ? *(const float4*)Ppl
                               : make_float4(0.f, 0.f, 0.f, 0.f);
        if (gInt) {
            #pragma unroll
            for (int c = 0; c < 6; c++) {            // 6 chunks of 8 neighbors
                float sv[8], cv[8];
                #pragma unroll
                for (int n = 0; n < 8; n++) {
                    int k  = c * 8 + n;              // compile-time
                    int dy = k / KK - 3;
                    int dx = k - (k / KK) * KK - 3;
                    int off = dy * WW + dx;
                    float4 nf = *(const float4*)(Pl + (ptrdiff_t)off * FB);
                    sv[n] = dot4(f, nf);
                    float4 np = (lane < 5)
                        ? *(const float4*)(Ppl + (ptrdiff_t)off * PB)
                        : make_float4(0.f, 0.f, 0.f, 0.f);
                    cv[n] = dot4(pc, np);
                }
                float s0 = tree8(sv, gmask, lane);
                float c0 = tree8(cv, gmask, lane);
                if (!(lane & 1)) {
                    int k = c * 8 + (lane >> 1);
                    sm_s[k][q] = s0;
                    sm_c[k][q] = c0;
                }
            }
            {   // straggler k = 48 (dy=3, dx=3)
                int off = 3 * WW + 3;
                float4 nf = *(const float4*)(Pl + (ptrdiff_t)off * FB);
                float pd = dot4(f, nf);
                float4 np = (lane < 5)
                    ? *(const float4*)(Ppl + (ptrdiff_t)off * PB)
                    : make_float4(0.f, 0.f, 0.f, 0.f);
                float pq = dot4(pc, np);
                #pragma unroll
                for (int o = 8; o; o >>= 1) {
                    pd += __shfl_xor_sync(gmask, pd, o);
                    pq += __shfl_xor_sync(gmask, pq, o);
                }
                if (lane == 0) { sm_s[48][q] = pd; sm_c[48][q] = pq; }
            }
        } else {
            int k = 0;
            #pragma unroll 1
            for (int ky = 0; ky < KK; ky++) {
                int hn = h + ky - 3;
                bool rv = (unsigned)hn < (unsigned)HH;
                int hc = min(max(hn, 0), HH - 1);
                #pragma unroll
                for (int kx = 0; kx < KK; kx++, k++) {
                    int wn = w + kx - 3;
                    bool ok = rv && ((unsigned)wn < (unsigned)WW);
                    int wc = min(max(wn, 0), WW - 1);
                    int pn = b * HWp + hc * WW + wc;
                    float4 nf = *(const float4*)((const char*)g_x + (size_t)pn * FB + lane * 16);
                    float pd = dot4(f, nf);
                    float4 np = (lane < 5)
                        ? *(const float4*)((const char*)g_pp + (size_t)pn * PB + lane * 16)
                        : make_float4(0.f, 0.f, 0.f, 0.f);
                    float pq = dot4(pc, np);
                    #pragma unroll
                    for (int o = 8; o; o >>= 1) {
                        pd += __shfl_xor_sync(gmask, pd, o);
                        pq += __shfl_xor_sync(gmask, pq, o);
                    }
                    if (lane == 0) {
                        sm_s[k][q] = ok ? pd : 0.f;
                        sm_c[k][q] = ok ? pq : (1.f / 19.f);
                    }
                }
            }
        }
    }
    __syncthreads();

    // ---- phase 2: thread t<32 = top-9 of pixel t; t>=32 = bottom-8 ----
    int t = threadIdx.x;
    int q2 = t & 31;
    int h2 = h0 + (q2 >> 2), w2 = w0 + (q2 & 3);
    int p2 = b * HWp + h2 * WW + w2;
    float ssp = 0.f, ssn = 0.f, cnt = 0.f;
    if ((1.f - mix[p2]) > 0.5f) {
        if (t < 32) {
            cnt = 1.f;
            float tv[NTOP], tc[NTOP];
            #pragma unroll
            for (int i = 0; i < NTOP; i++) { tv[i] = -3.4e38f; tc[i] = 0.f; }
            #pragma unroll 1
            for (int k = 0; k < K2; k++) {
                float vs = sm_s[k][q2];
                float vc = sm_c[k][q2];
                if (vs > tv[NTOP - 1]) {           // guard: skip non-contenders
                    #pragma unroll
                    for (int i = 0; i < NTOP; i++) {   // strict > : JAX tie-break
                        if (vs > tv[i]) {
                            float x = tv[i]; tv[i] = vs; vs = x;
                            x = tc[i]; tc[i] = vc; vc = x;
                        }
                    }
                }
            }
            #pragma unroll
            for (int i = 0; i < NTOP; i++) ssp = fmaf(tv[i], -tc[i], ssp);
        } else {
            float bv[NBOT], bc[NBOT];
            #pragma unroll
            for (int i = 0; i < NBOT; i++) { bv[i] = 3.4e38f; bc[i] = 0.f; }
            #pragma unroll 1
            for (int k = 0; k < K2; k++) {
                float us = sm_s[k][q2];
                float uc = sm_c[k][q2];
                if (us < bv[NBOT - 1]) {
                    #pragma unroll
                    for (int i = 0; i < NBOT; i++) {   // strict <
                        if (us < bv[i]) {
                            float x = bv[i]; bv[i] = us; us = x;
                            x = bc[i]; bc[i] = uc; uc = x;
                        }
                    }
                }
            }
            #pragma unroll
            for (int i = 0; i < NBOT; i++) ssn += (1.f - bv[i]) * (-(1.f - bc[i]));
        }
    }
    #pragma unroll
    for (int o = 16; o; o >>= 1) {
        ssp += __shfl_xor_sync(0xffffffffu, ssp, o);
        ssn += __shfl_xor_sync(0xffffffffu, ssn, o);
        cnt += __shfl_xor_sync(0xffffffffu, cnt, o);
    }
    if ((t & 31) == 0) {
        int wp = t >> 5;
        red[wp * 3 + 0] = ssp;
        red[wp * 3 + 1] = ssn;
        red[wp * 3 + 2] = cnt;
    }
    __syncthreads();
    if (t == 0) {
        atomicAdd(&g_acc[4], (double)(red[0] + red[3]));
        atomicAdd(&g_acc[5], (double)(red[1] + red[4]));
        atomicAdd(&g_acc[6], (double)(red[2] + red[5]));
    }
}

__global__ void k_final(float* __restrict__ out) {
    if (threadIdx.x != 0) return;
    double src_pos = g_acc[0] / fmax(g_acc[1], 1.0);
    double src_neg = g_acc[2] / fmax(g_acc[3], 1.0);
    double sim_pos = g_acc[4] / fmax((double)NTOP * g_acc[6], 1.0);
    double sim_neg = g_acc[5] / fmax((double)NBOT * g_acc[6], 1.0);
    out[0] = (float)(-src_pos);
    out[1] = (float)( src_neg);
    out[2] = (float)( sim_pos);
    out[3] = (float)( sim_neg);
}

extern "C" void kernel_launch(void* const* d_in, const int* in_sizes, int n_in,
                              void* d_out, int out_size) {
    (void)in_sizes; (void)n_in; (void)out_size;
    const float* logits = (const float*)d_in[0];
    const int*   gt     = (const int*)d_in[1];
    const float* xe     = (const float*)d_in[2];
    const float* xs     = (const float*)d_in[3];
    const float* mix    = (const float*)d_in[4];
    float* out = (float*)d_out;

    k_soft<<<NPIX / 256, 256>>>(logits);   // also zeroes g_acc
    k_tr<<<NPIX / 32, 256>>>(xs);          // g_x <- normalized x_src
    k_src<<<1024, 512>>>(gt);
    k_tr<<<NPIX / 32, 256>>>(xe);          // g_x <- normalized x_ema
    k_trg<<<1024, 64>>>(mix);
    k_final<<<1, 32>>>(out);
}

// round 6
// speedup vs baseline: 1.1633x; 1.1633x over previous
#include <cuda_runtime.h>
#include <math.h>

// ---------------------------------------------------------------------------
// LocalPseudoFeatLoss: B=2, C=19, H=W=128, CH=64, K=7, TOPK=8
// ---------------------------------------------------------------------------

namespace {
constexpr int NC   = 19;
constexpr int NCP  = 20;     // padded classes
constexpr int HH   = 128;
constexpr int WW   = 128;
constexpr int HWp  = HH * WW;
constexpr int FC   = 64;
constexpr int KK   = 7;
constexpr int K2   = KK * KK;
constexpr int NTOP = 9;
constexpr int NBOT = 8;
constexpr int NPIX = 2 * HWp;
constexpr float EPSV = 1e-8f;
constexpr int FB = FC * 4;    // feature row bytes
constexpr int PB = NCP * 4;   // prob row bytes
}

__device__ float  g_x[NPIX * FC];      // PRE-NORMALIZED features (src, then ema)
__device__ float  g_pp[NPIX * NCP];    // softmax(logits), pixel-major, padded
__device__ double g_acc[8];
// 0 sum_src_pos 1 cnt_src_pos 2 sum_src_neg 3 cnt_src_neg
// 4 sum_sim_pos 5 sum_sim_neg 6 cnt_trg

__device__ __forceinline__ float dot4(float4 a, float4 b) {
    float d = a.x * b.x;
    d = fmaf(a.y, b.y, d);
    d = fmaf(a.z, b.z, d);
    d = fmaf(a.w, b.w, d);
    return d;
}

// ordered-uint encoding: monotone float -> uint
__device__ __forceinline__ unsigned ord_of_f(float f) {
    unsigned b = __float_as_uint(f);
    return b ^ (((unsigned)((int)b >> 31)) | 0x80000000u);
}
__device__ __forceinline__ float f_of_ord(unsigned u) {
    unsigned b = (u & 0x80000000u) ? (u ^ 0x80000000u) : ~u;
    return __uint_as_float(b);
}

// Reduce 8 values across 16 lanes (segmented exchange tree).
// On return, lanes {2n, 2n+1} both hold total of value n.
__device__ __forceinline__ float tree8(float v[8], unsigned mask, int lane) {
    {   bool hi = (lane & 8) != 0;
        #pragma unroll
        for (int j = 0; j < 4; j++) {
            float mine = hi ? v[j] : v[j + 4];
            float kept = hi ? v[j + 4] : v[j];
            v[j] = kept + __shfl_xor_sync(mask, mine, 8);
        } }
    {   bool hi = (lane & 4) != 0;
        #pragma unroll
        for (int j = 0; j < 2; j++) {
            float mine = hi ? v[j] : v[j + 2];
            float kept = hi ? v[j + 2] : v[j];
            v[j] = kept + __shfl_xor_sync(mask, mine, 4);
        } }
    {   bool hi = (lane & 2) != 0;
        float mine = hi ? v[0] : v[1];
        float kept = hi ? v[1] : v[0];
        v[0] = kept + __shfl_xor_sync(mask, mine, 2);
    }
    v[0] += __shfl_xor_sync(mask, v[0], 1);
    return v[0];
}

// transpose [C][HW] -> [pix][C], PRE-NORMALIZED by 1/max(||x||,eps)
__global__ void __launch_bounds__(256)
k_tr(const float* __restrict__ src) {
    __shared__ float sm[FC][33];
    int pix0 = blockIdx.x * 32;
    int b   = pix0 / HWp;
    int hw0 = pix0 - b * HWp;
    int t = threadIdx.x;

    int px = t & 31, cb = (t >> 5) * 8;
    const float* sp = src + (size_t)b * FC * HWp + hw0 + px;
    #pragma unroll
    for (int j = 0; j < 8; j++)
        sm[cb + j][px] = sp[(size_t)(cb + j) * HWp];
    __syncthreads();

    int px2 = t >> 3, part = t & 7;
    float v[8];
    float ss = 0.f;
    #pragma unroll
    for (int j = 0; j < 8; j++) {
        v[j] = sm[part * 8 + j][px2];
        ss = fmaf(v[j], v[j], ss);
    }
    #pragma unroll
    for (int o = 4; o; o >>= 1) ss += __shfl_xor_sync(0xffffffffu, ss, o);
    float rn = 1.f / fmaxf(sqrtf(ss), EPSV);
    float4* d = reinterpret_cast<float4*>(g_x + (size_t)(pix0 + px2) * FC + part * 8);
    d[0] = make_float4(v[0] * rn, v[1] * rn, v[2] * rn, v[3] * rn);
    d[1] = make_float4(v[4] * rn, v[5] * rn, v[6] * rn, v[7] * rn);
}

// softmax per pixel -> pixel-major padded (+ zero the accumulators)
__global__ void __launch_bounds__(256)
k_soft(const float* __restrict__ logits) {
    if (blockIdx.x == 0 && threadIdx.x < 8) g_acc[threadIdx.x] = 0.0;
    int pix = blockIdx.x * blockDim.x + threadIdx.x;
    if (pix >= NPIX) return;
    int b  = pix / HWp;
    int hw = pix - b * HWp;
    const float* lb = logits + (size_t)b * NC * HWp + hw;
    float l[NC];
    float mx = -3.4e38f;
    #pragma unroll
    for (int c = 0; c < NC; c++) {
        l[c] = lb[(size_t)c * HWp];
        mx = fmaxf(mx, l[c]);
    }
    float s = 0.f;
    #pragma unroll
    for (int c = 0; c < NC; c++) { l[c] = expf(l[c] - mx); s += l[c]; }
    float inv = 1.f / s;
    #pragma unroll
    for (int c = 0; c < NC; c++) g_pp[(size_t)pix * NCP + c] = l[c] * inv;
    g_pp[(size_t)pix * NCP + NC] = 0.f;
}

// ---- source loss: 16 lanes/pixel, deferred reduce, interior fast path ----
__global__ void __launch_bounds__(512)
k_src(const int* __restrict__ gt) {
    int bx = blockIdx.x;
    int b  = bx >> 9;
    int tt = bx & 511;
    int h0 = (tt >> 4) << 2;     // 32 h-tiles of 4
    int w0 = (tt & 15) << 3;     // 16 w-tiles of 8
    int g    = threadIdx.x >> 4;
    int lane = threadIdx.x & 15;
    unsigned gmask = 0xFFFFu << (threadIdx.x & 16);
    int h = h0 + (g >> 3), w = w0 + (g & 7);
    int pix = b * HWp + h * WW + w;

    bool interior = (h0 >= 4) && (h0 <= 120) && (w0 >= 8) && (w0 <= 112);

    float sp = 0.f, sn = 0.f;
    float cp = 0.f, cn = 0.f;
    int gc = gt[pix];
    if (gc != 255) {
        const char* Pl = (const char*)g_x + (size_t)pix * FB + lane * 16;
        float4 f = *(const float4*)Pl;
        if (interior) {
            float tot = 0.f, spp = 0.f;
            int cpp = 0;
            #pragma unroll 1
            for (int ky = 0; ky < KK; ky++) {
                const char* Pr = Pl + (ptrdiff_t)(ky - 3) * (WW * FB);
                const int* Pg = gt + pix + (ky - 3) * WW;
                #pragma unroll
                for (int kx = 0; kx < KK; kx++) {
                    float4 nf = *(const float4*)(Pr + (kx - 3) * FB);
                    float s = dot4(f, nf);
                    int gn = Pg[kx - 3];
                    tot += s;
                    if (gn == gc) { spp += s; cpp++; }
                }
            }
            sp = spp; sn = tot - spp;
            cp = (float)cpp; cn = (float)(K2 - cpp);
        } else {
            int cpp = 0, cnn = 0;
            #pragma unroll 1
            for (int ky = 0; ky < KK; ky++) {
                int hn = h + ky - 3;
                bool rv = (unsigned)hn < (unsigned)HH;
                int hc = min(max(hn, 0), HH - 1);
                #pragma unroll
                for (int kx = 0; kx < KK; kx++) {
                    int wn = w + kx - 3;
                    bool ok = rv && ((unsigned)wn < (unsigned)WW);
                    int wc = min(max(wn, 0), WW - 1);
                    int pn = b * HWp + hc * WW + wc;
                    float4 nf = *(const float4*)((const char*)g_x + (size_t)pn * FB + lane * 16);
                    float s = dot4(f, nf);
                    int gn = gt[pn];
                    if (!ok) { s = 0.f; gn = 0; }
                    if (gn == gc) { sp += s; cpp++; }
                    else          { sn += s; cnn++; }
                }
            }
            cp = (float)cpp; cn = (float)cnn;
        }
        #pragma unroll
        for (int o = 8; o; o >>= 1) {
            sp += __shfl_xor_sync(gmask, sp, o);
            sn += __shfl_xor_sync(gmask, sn, o);
        }
    }
    __shared__ float sa[4];
    if (threadIdx.x < 4) sa[threadIdx.x] = 0.f;
    __syncthreads();
    if (gc != 255 && lane == 0) {
        atomicAdd(&sa[0], sp);
        atomicAdd(&sa[1], cp);
        atomicAdd(&sa[2], sn);
        atomicAdd(&sa[3], cn);
    }
    __syncthreads();
    if (threadIdx.x == 0) {
        atomicAdd(&g_acc[0], (double)sa[0]);
        atomicAdd(&g_acc[1], (double)sa[1]);
        atomicAdd(&g_acc[2], (double)sa[2]);
        atomicAdd(&g_acc[3], (double)sa[3]);
    }
}

// ---- target, R4 skeleton (256 thr, 16 px/block), deferred cross-probs ----
// phase 1: sims only (16 lanes/pixel)
// phase 2a: top-9/bottom-8 on packed 64-bit keys (32 threads)
// phase 2b: 17 selected 20-dim prob dots per pixel (16 lanes/pixel)
__global__ void __launch_bounds__(256)
k_trg(const float* __restrict__ mix) {
    __shared__ float sm_s[K2][17];
    __shared__ unsigned long long sel[16][18];   // top keys [0..8], bottom [9..16]
    __shared__ float sred[3];

    int bx = blockIdx.x;              // 2048 blocks
    int b  = bx >> 10;
    int tt = bx & 1023;               // 32x32 tiles of 4x4
    int h0 = (tt >> 5) << 2;
    int w0 = (tt & 31) << 2;
    int g    = threadIdx.x >> 4;      // 0..15 pixel in tile
    int lane = threadIdx.x & 15;
    unsigned gmask = 0xFFFFu << (threadIdx.x & 16);
    int h = h0 + (g >> 2), w = w0 + (g & 3);
    int pix = b * HWp + h * WW + w;

    bool interior = (h0 >= 4) && (h0 <= 120) && (w0 >= 4) && (w0 <= 120);
    bool act = (1.f - mix[pix]) > 0.5f;

    // ---- phase 1: sims only ----
    if (act) {
        const char* Pl = (const char*)g_x + (size_t)pix * FB + lane * 16;
        float4 f = *(const float4*)Pl;
        if (interior) {
            #pragma unroll
            for (int c = 0; c < 6; c++) {            // 6 chunks of 8 neighbors
                float sv[8];
                #pragma unroll
                for (int n = 0; n < 8; n++) {
                    int k  = c * 8 + n;              // compile-time
                    int dy = k / KK - 3;
                    int dx = k - (k / KK) * KK - 3;
                    int off = dy * WW + dx;
                    float4 nf = *(const float4*)(Pl + (ptrdiff_t)off * FB);
                    sv[n] = dot4(f, nf);
                }
                float s0 = tree8(sv, gmask, lane);
                if (!(lane & 1)) sm_s[c * 8 + (lane >> 1)][g] = s0;
            }
            {   // straggler k = 48 (dy=3, dx=3)
                float4 nf = *(const float4*)(Pl + (ptrdiff_t)(3 * WW + 3) * FB);
                float pd = dot4(f, nf);
                #pragma unroll
                for (int o = 8; o; o >>= 1)
                    pd += __shfl_xor_sync(gmask, pd, o);
                if (lane == 0) sm_s[48][g] = pd;
            }
        } else {
            int k = 0;
            #pragma unroll 1
            for (int ky = 0; ky < KK; ky++) {
                int hn = h + ky - 3;
                bool rv = (unsigned)hn < (unsigned)HH;
                int hc = min(max(hn, 0), HH - 1);
                #pragma unroll
                for (int kx = 0; kx < KK; kx++, k++) {
                    int wn = w + kx - 3;
                    bool ok = rv && ((unsigned)wn < (unsigned)WW);
                    int wc = min(max(wn, 0), WW - 1);
                    int pn = b * HWp + hc * WW + wc;
                    float4 nf = *(const float4*)((const char*)g_x + (size_t)pn * FB + lane * 16);
                    float pd = dot4(f, nf);
                    #pragma unroll
                    for (int o = 8; o; o >>= 1)
                        pd += __shfl_xor_sync(gmask, pd, o);
                    if (lane == 0) sm_s[k][g] = ok ? pd : 0.f;
                }
            }
        }
    }
    if (threadIdx.x < 3) sred[threadIdx.x] = 0.f;
    __syncthreads();

    // ---- phase 2a: selection on packed keys (32 threads) ----
    if (threadIdx.x < 32) {
        int t = threadIdx.x;
        int q2 = t & 15;
        int h2 = h0 + (q2 >> 2), w2 = w0 + (q2 & 3);
        int p2 = b * HWp + h2 * WW + w2;
        if ((1.f - mix[p2]) > 0.5f) {
            if (t < 16) {           // top-9: key desc = sim desc, k asc
                unsigned long long key[NTOP];
                #pragma unroll
                for (int i = 0; i < NTOP; i++) key[i] = 0ull;
                #pragma unroll 1
                for (int k = 0; k < K2; k++) {
                    unsigned long long kk =
                        ((unsigned long long)ord_of_f(sm_s[k][q2]) << 8)
                        | (unsigned)(63 - k);
                    if (kk > key[NTOP - 1]) {
                        #pragma unroll
                        for (int i = 0; i < NTOP; i++)
                            if (kk > key[i]) {
                                unsigned long long x = key[i]; key[i] = kk; kk = x;
                            }
                    }
                }
                #pragma unroll
                for (int i = 0; i < NTOP; i++) sel[q2][i] = key[i];
            } else {                // bottom-8: key asc = sim asc, k asc
                unsigned long long key[NBOT];
                #pragma unroll
                for (int i = 0; i < NBOT; i++) key[i] = ~0ull;
                #pragma unroll 1
                for (int k = 0; k < K2; k++) {
                    unsigned long long kk =
                        ((unsigned long long)ord_of_f(sm_s[k][q2]) << 8)
                        | (unsigned)k;
                    if (kk < key[NBOT - 1]) {
                        #pragma unroll
                        for (int i = 0; i < NBOT; i++)
                            if (kk < key[i]) {
                                unsigned long long x = key[i]; key[i] = kk; kk = x;
                            }
                    }
                }
                #pragma unroll
                for (int i = 0; i < NBOT; i++) sel[q2][NTOP + i] = key[i];
            }
        }
    }
    __syncthreads();

    // ---- phase 2b: 17 selected prob dots per pixel (16 lanes/pixel) ----
    float ssp = 0.f, ssn = 0.f, cnt = 0.f;
    if (act) {
        if (lane == 0) cnt = 1.f;
        const float4* A = reinterpret_cast<const float4*>(g_pp + (size_t)pix * NCP);
        #pragma unroll 1
        for (int tid = lane; tid < NTOP + NBOT; tid += 16) {
            unsigned long long kk = sel[g][tid];
            bool isTop = tid < NTOP;
            int k = isTop ? (63 - (int)(kk & 63u)) : (int)(kk & 63u);
            float val = f_of_ord((unsigned)(kk >> 8));
            int dy = ((k * 9363) >> 16) - 3;
            int dx = k - (dy + 3) * KK - 3;
            int hn = h + dy, wn = w + dx;
            float cp = 1.f / 19.f;
            if ((unsigned)hn < (unsigned)HH && (unsigned)wn < (unsigned)WW) {
                const float4* Bv = reinterpret_cast<const float4*>(
                    g_pp + (size_t)(pix + dy * WW + dx) * NCP);
                float d2 = 0.f;
                #pragma unroll
                for (int i = 0; i < 5; i++) d2 += dot4(A[i], Bv[i]);
                cp = d2;
            }
            if (isTop) ssp = fmaf(val, -cp, ssp);
            else       ssn += (1.f - val) * (-(1.f - cp));
        }
    }
    #pragma unroll
    for (int o = 16; o; o >>= 1) {
        ssp += __shfl_xor_sync(0xffffffffu, ssp, o);
        ssn += __shfl_xor_sync(0xffffffffu, ssn, o);
        cnt += __shfl_xor_sync(0xffffffffu, cnt, o);
    }
    if ((threadIdx.x & 31) == 0) {
        atomicAdd(&sred[0], ssp);
        atomicAdd(&sred[1], ssn);
        atomicAdd(&sred[2], cnt);
    }
    __syncthreads();
    if (threadIdx.x == 0) {
        atomicAdd(&g_acc[4], (double)sred[0]);
        atomicAdd(&g_acc[5], (double)sred[1]);
        atomicAdd(&g_acc[6], (double)sred[2]);
    }
}

__global__ void k_final(float* __restrict__ out) {
    if (threadIdx.x != 0) return;
    double src_pos = g_acc[0] / fmax(g_acc[1], 1.0);
    double src_neg = g_acc[2] / fmax(g_acc[3], 1.0);
    double sim_pos = g_acc[4] / fmax((double)NTOP * g_acc[6], 1.0);
    double sim_neg = g_acc[5] / fmax((double)NBOT * g_acc[6], 1.0);
    out[0] = (float)(-src_pos);
    out[1] = (float)( src_neg);
    out[2] = (float)( sim_pos);
    out[3] = (float)( sim_neg);
}

extern "C" void kernel_launch(void* const* d_in, const int* in_sizes, int n_in,
                              void* d_out, int out_size) {
    (void)in_sizes; (void)n_in; (void)out_size;
    const float* logits = (const float*)d_in[0];
    const int*   gt     = (const int*)d_in[1];
    const float* xe     = (const float*)d_in[2];
    const float* xs     = (const float*)d_in[3];
    const float* mix    = (const float*)d_in[4];
    float* out = (float*)d_out;

    k_soft<<<NPIX / 256, 256>>>(logits);   // also zeroes g_acc
    k_tr<<<NPIX / 32, 256>>>(xs);          // g_x <- normalized x_src
    k_src<<<1024, 512>>>(gt);
    k_tr<<<NPIX / 32, 256>>>(xe);          // g_x <- normalized x_ema
    k_trg<<<2048, 256>>>(mix);
    k_final<<<1, 32>>>(out);
}

// round 7
// speedup vs baseline: 1.2060x; 1.0366x over previous
#include <cuda_runtime.h>
#include <math.h>

// ---------------------------------------------------------------------------
// LocalPseudoFeatLoss: B=2, C=19, H=W=128, CH=64, K=7, TOPK=8
// ---------------------------------------------------------------------------

namespace {
constexpr int NC   = 19;
constexpr int NCP  = 20;     // padded classes
constexpr int HH   = 128;
constexpr int WW   = 128;
constexpr int HWp  = HH * WW;
constexpr int FC   = 64;
constexpr int KK   = 7;
constexpr int K2   = KK * KK;
constexpr int NTOP = 9;
constexpr int NBOT = 8;
constexpr int NPIX = 2 * HWp;
constexpr float EPSV = 1e-8f;
constexpr int FB = FC * 4;    // feature row bytes
constexpr int PB = NCP * 4;   // prob row bytes
constexpr int NT = NPIX / 32; // transpose blocks per tensor (1024)
}

__device__ float  g_xs[NPIX * FC];     // normalized x_src, pixel-major
__device__ float  g_xe[NPIX * FC];     // normalized x_ema, pixel-major
__device__ float  g_pp[NPIX * NCP];    // softmax(logits), pixel-major, padded
__device__ double g_acc[8];
// 0 sum_src_pos  1 cnt_src_pos  2 sum_src_neg  3 n_valid_src
// 4 sum_sim_pos  5 sum_sim_neg  6 cnt_trg

__device__ __forceinline__ float dot4(float4 a, float4 b) {
    float d = a.x * b.x;
    d = fmaf(a.y, b.y, d);
    d = fmaf(a.z, b.z, d);
    d = fmaf(a.w, b.w, d);
    return d;
}

// ordered-uint encoding: monotone float -> uint
__device__ __forceinline__ unsigned ord_of_f(float f) {
    unsigned b = __float_as_uint(f);
    return b ^ (((unsigned)((int)b >> 31)) | 0x80000000u);
}
__device__ __forceinline__ float f_of_ord(unsigned u) {
    unsigned b = (u & 0x80000000u) ? (u ^ 0x80000000u) : ~u;
    return __uint_as_float(b);
}

// Reduce 8 values across 16 lanes (segmented exchange tree).
// On return, lanes {2n, 2n+1} both hold total of value n.
__device__ __forceinline__ float tree8(float v[8], unsigned mask, int lane) {
    {   bool hi = (lane & 8) != 0;
        #pragma unroll
        for (int j = 0; j < 4; j++) {
            float mine = hi ? v[j] : v[j + 4];
            float kept = hi ? v[j + 4] : v[j];
            v[j] = kept + __shfl_xor_sync(mask, mine, 8);
        } }
    {   bool hi = (lane & 4) != 0;
        #pragma unroll
        for (int j = 0; j < 2; j++) {
            float mine = hi ? v[j] : v[j + 2];
            float kept = hi ? v[j + 2] : v[j];
            v[j] = kept + __shfl_xor_sync(mask, mine, 4);
        } }
    {   bool hi = (lane & 2) != 0;
        float mine = hi ? v[0] : v[1];
        float kept = hi ? v[1] : v[0];
        v[0] = kept + __shfl_xor_sync(mask, mine, 2);
    }
    v[0] += __shfl_xor_sync(mask, v[0], 1);
    return v[0];
}

// ---- fused prep: blocks [0,NT) transpose xs, [NT,2NT) xe, rest softmax ----
__device__ __forceinline__ void transpose_block(const float* __restrict__ src,
                                                float* __restrict__ dst,
                                                int blk, int t) {
    __shared__ float sm[FC][33];
    int pix0 = blk * 32;
    int b   = pix0 / HWp;
    int hw0 = pix0 - b * HWp;

    int px = t & 31, cb = (t >> 5) * 8;
    const float* sp = src + (size_t)b * FC * HWp + hw0 + px;
    #pragma unroll
    for (int j = 0; j < 8; j++)
        sm[cb + j][px] = sp[(size_t)(cb + j) * HWp];
    __syncthreads();

    int px2 = t >> 3, part = t & 7;
    float v[8];
    float ss = 0.f;
    #pragma unroll
    for (int j = 0; j < 8; j++) {
        v[j] = sm[part * 8 + j][px2];
        ss = fmaf(v[j], v[j], ss);
    }
    #pragma unroll
    for (int o = 4; o; o >>= 1) ss += __shfl_xor_sync(0xffffffffu, ss, o);
    float rn = 1.f / fmaxf(sqrtf(ss), EPSV);
    float4* d = reinterpret_cast<float4*>(dst + (size_t)(pix0 + px2) * FC + part * 8);
    d[0] = make_float4(v[0] * rn, v[1] * rn, v[2] * rn, v[3] * rn);
    d[1] = make_float4(v[4] * rn, v[5] * rn, v[6] * rn, v[7] * rn);
}

__global__ void __launch_bounds__(256)
k_prep(const float* __restrict__ xs, const float* __restrict__ xe,
       const float* __restrict__ logits) {
    int bx = blockIdx.x;
    int t = threadIdx.x;
    if (bx < NT) {
        transpose_block(xs, g_xs, bx, t);
    } else if (bx < 2 * NT) {
        transpose_block(xe, g_xe, bx - NT, t);
    } else {
        int sb = bx - 2 * NT;
        if (sb == 0 && t < 8) g_acc[t] = 0.0;
        int pix = sb * 256 + t;
        if (pix >= NPIX) return;
        int b  = pix / HWp;
        int hw = pix - b * HWp;
        const float* lb = logits + (size_t)b * NC * HWp + hw;
        float l[NC];
        float mx = -3.4e38f;
        #pragma unroll
        for (int c = 0; c < NC; c++) {
            l[c] = lb[(size_t)c * HWp];
            mx = fmaxf(mx, l[c]);
        }
        float s = 0.f;
        #pragma unroll
        for (int c = 0; c < NC; c++) { l[c] = expf(l[c] - mx); s += l[c]; }
        float inv = 1.f / s;
        #pragma unroll
        for (int c = 0; c < NC; c++) g_pp[(size_t)pix * NCP + c] = l[c] * inv;
        g_pp[(size_t)pix * NCP + NC] = 0.f;
    }
}

// ---- source loss, pair-symmetric: 24 forward neighbors + analytic center ----
// Each unordered pair {p,q} contributes sim * [(gt[p]!=255)+(gt[q]!=255)]
// to pos (gt[p]==gt[q]) or neg. Counts are decoupled (gt-only loop).
__global__ void __launch_bounds__(512)
k_src(const int* __restrict__ gt) {
    int bx = blockIdx.x;
    int b  = bx >> 9;
    int tt = bx & 511;
    int h0 = (tt >> 4) << 2;     // 32 h-tiles of 4
    int w0 = (tt & 15) << 3;     // 16 w-tiles of 8
    int g    = threadIdx.x >> 4;
    int lane = threadIdx.x & 15;
    unsigned gmask = 0xFFFFu << (threadIdx.x & 16);
    int h = h0 + (g >> 3), w = w0 + (g & 7);
    int pix = b * HWp + h * WW + w;

    bool interior = (h0 >= 4) && (h0 <= 120) && (w0 >= 8) && (w0 <= 112);

    int gc = gt[pix];
    float wp = (gc != 255) ? 1.f : 0.f;

    float sp = 0.f, sn = 0.f, cp = 0.f, nv = 0.f;

    const char* Pl = (const char*)g_xs + (size_t)pix * FB + lane * 16;
    float4 f = *(const float4*)Pl;
    const int* Pg = gt + pix;

    // --- pair-sim loop over 24 forward neighbors (k = 25..48) ---
    if (interior) {
        #pragma unroll
        for (int c = 0; c < 3; c++) {
            #pragma unroll
            for (int n = 0; n < 8; n++) {
                int k  = 25 + c * 8 + n;         // compile-time
                int dy = k / KK - 3;
                int dx = k - (k / KK) * KK - 3;
                int off = dy * WW + dx;
                float4 nf = *(const float4*)(Pl + (ptrdiff_t)off * FB);
                float s = dot4(f, nf);
                int gq = Pg[off];
                float wgt = wp + ((gq != 255) ? 1.f : 0.f);
                if (gq == gc) sp = fmaf(wgt, s, sp);
                else          sn = fmaf(wgt, s, sn);
            }
        }
    } else {
        #pragma unroll 1
        for (int k = 25; k < K2; k++) {
            int dy = k / KK - 3;
            int dx = k - (k / KK) * KK - 3;
            int hn = h + dy, wn = w + dx;
            if ((unsigned)hn < (unsigned)HH && (unsigned)wn < (unsigned)WW) {
                int off = dy * WW + dx;
                float4 nf = *(const float4*)(Pl + (ptrdiff_t)off * FB);
                float s = dot4(f, nf);
                int gq = Pg[off];
                float wgt = wp + ((gq != 255) ? 1.f : 0.f);
                if (gq == gc) sp = fmaf(wgt, s, sp);
                else          sn = fmaf(wgt, s, sn);
            }
        }
    }
    if (lane == 0) {
        sp += wp;        // center pair (k=24): sim = 1, pos
        nv  = wp;
    }

    // --- count loop (gt-only), distributed over lanes ---
    if (gc != 255) {
        if (interior) {
            #pragma unroll 1
            for (int k = lane; k < K2; k += 16) {
                int dy = ((k * 9363) >> 16) - 3;       // k/7 - 3
                int dx = k - (dy + 3) * KK - 3;
                int gn = Pg[dy * WW + dx];
                if (gn == gc) cp += 1.f;
            }
        } else {
            #pragma unroll 1
            for (int k = lane; k < K2; k += 16) {
                int dy = ((k * 9363) >> 16) - 3;
                int dx = k - (dy + 3) * KK - 3;
                int hn = h + dy, wn = w + dx;
                int gn = 0;
                if ((unsigned)hn < (unsigned)HH && (unsigned)wn < (unsigned)WW)
                    gn = Pg[dy * WW + dx];
                if (gn == gc) cp += 1.f;
            }
        }
    }

    #pragma unroll
    for (int o = 8; o; o >>= 1) {
        sp += __shfl_xor_sync(gmask, sp, o);
        sn += __shfl_xor_sync(gmask, sn, o);
        cp += __shfl_xor_sync(gmask, cp, o);
        nv += __shfl_xor_sync(gmask, nv, o);
    }
    __shared__ float sa[4];
    if (threadIdx.x < 4) sa[threadIdx.x] = 0.f;
    __syncthreads();
    if (lane == 0) {
        atomicAdd(&sa[0], sp);
        atomicAdd(&sa[1], cp);
        atomicAdd(&sa[2], sn);
        atomicAdd(&sa[3], nv);
    }
    __syncthreads();
    if (threadIdx.x == 0) {
        atomicAdd(&g_acc[0], (double)sa[0]);
        atomicAdd(&g_acc[1], (double)sa[1]);
        atomicAdd(&g_acc[2], (double)sa[2]);
        atomicAdd(&g_acc[3], (double)sa[3]);
    }
}

// ---- target (R6 structure, reads g_xe): sims -> key top-k -> selected cps ----
__global__ void __launch_bounds__(256)
k_trg(const float* __restrict__ mix) {
    __shared__ float sm_s[K2][17];
    __shared__ unsigned long long sel[16][18];   // top keys [0..8], bottom [9..16]
    __shared__ float sred[3];

    int bx = blockIdx.x;              // 2048 blocks
    int b  = bx >> 10;
    int tt = bx & 1023;               // 32x32 tiles of 4x4
    int h0 = (tt >> 5) << 2;
    int w0 = (tt & 31) << 2;
    int g    = threadIdx.x >> 4;      // 0..15 pixel in tile
    int lane = threadIdx.x & 15;
    unsigned gmask = 0xFFFFu << (threadIdx.x & 16);
    int h = h0 + (g >> 2), w = w0 + (g & 3);
    int pix = b * HWp + h * WW + w;

    bool interior = (h0 >= 4) && (h0 <= 120) && (w0 >= 4) && (w0 <= 120);
    bool act = (1.f - mix[pix]) > 0.5f;

    // ---- phase 1: sims only ----
    if (act) {
        const char* Pl = (const char*)g_xe + (size_t)pix * FB + lane * 16;
        float4 f = *(const float4*)Pl;
        if (interior) {
            #pragma unroll
            for (int c = 0; c < 6; c++) {            // 6 chunks of 8 neighbors
                float sv[8];
                #pragma unroll
                for (int n = 0; n < 8; n++) {
                    int k  = c * 8 + n;              // compile-time
                    int dy = k / KK - 3;
                    int dx = k - (k / KK) * KK - 3;
                    int off = dy * WW + dx;
                    float4 nf = *(const float4*)(Pl + (ptrdiff_t)off * FB);
                    sv[n] = dot4(f, nf);
                }
                float s0 = tree8(sv, gmask, lane);
                if (!(lane & 1)) sm_s[c * 8 + (lane >> 1)][g] = s0;
            }
            {   // straggler k = 48 (dy=3, dx=3)
                float4 nf = *(const float4*)(Pl + (ptrdiff_t)(3 * WW + 3) * FB);
                float pd = dot4(f, nf);
                #pragma unroll
                for (int o = 8; o; o >>= 1)
                    pd += __shfl_xor_sync(gmask, pd, o);
                if (lane == 0) sm_s[48][g] = pd;
            }
        } else {
            int k = 0;
            #pragma unroll 1
            for (int ky = 0; ky < KK; ky++) {
                int hn = h + ky - 3;
                bool rv = (unsigned)hn < (unsigned)HH;
                int hc = min(max(hn, 0), HH - 1);
                #pragma unroll
                for (int kx = 0; kx < KK; kx++, k++) {
                    int wn = w + kx - 3;
                    bool ok = rv && ((unsigned)wn < (unsigned)WW);
                    int wc = min(max(wn, 0), WW - 1);
                    int pn = b * HWp + hc * WW + wc;
                    float4 nf = *(const float4*)((const char*)g_xe + (size_t)pn * FB + lane * 16);
                    float pd = dot4(f, nf);
                    #pragma unroll
                    for (int o = 8; o; o >>= 1)
                        pd += __shfl_xor_sync(gmask, pd, o);
                    if (lane == 0) sm_s[k][g] = ok ? pd : 0.f;
                }
            }
        }
    }
    if (threadIdx.x < 3) sred[threadIdx.x] = 0.f;
    __syncthreads();

    // ---- phase 2a: selection on packed keys (32 threads) ----
    if (threadIdx.x < 32) {
        int t = threadIdx.x;
        int q2 = t & 15;
        int h2 = h0 + (q2 >> 2), w2 = w0 + (q2 & 3);
        int p2 = b * HWp + h2 * WW + w2;
        if ((1.f - mix[p2]) > 0.5f) {
            if (t < 16) {           // top-9: key desc = sim desc, k asc
                unsigned long long key[NTOP];
                #pragma unroll
                for (int i = 0; i < NTOP; i++) key[i] = 0ull;
                #pragma unroll 1
                for (int k = 0; k < K2; k++) {
                    unsigned long long kk =
                        ((unsigned long long)ord_of_f(sm_s[k][q2]) << 8)
                        | (unsigned)(63 - k);
                    if (kk > key[NTOP - 1]) {
                        #pragma unroll
                        for (int i = 0; i < NTOP; i++)
                            if (kk > key[i]) {
                                unsigned long long x = key[i]; key[i] = kk; kk = x;
                            }
                    }
                }
                #pragma unroll
                for (int i = 0; i < NTOP; i++) sel[q2][i] = key[i];
            } else {                // bottom-8: key asc = sim asc, k asc
                unsigned long long key[NBOT];
                #pragma unroll
                for (int i = 0; i < NBOT; i++) key[i] = ~0ull;
                #pragma unroll 1
                for (int k = 0; k < K2; k++) {
                    unsigned long long kk =
                        ((unsigned long long)ord_of_f(sm_s[k][q2]) << 8)
                        | (unsigned)k;
                    if (kk < key[NBOT - 1]) {
                        #pragma unroll
                        for (int i = 0; i < NBOT; i++)
                            if (kk < key[i]) {
                                unsigned long long x = key[i]; key[i] = kk; kk = x;
                            }
                    }
                }
                #pragma unroll
                for (int i = 0; i < NBOT; i++) sel[q2][NTOP + i] = key[i];
            }
        }
    }
    __syncthreads();

    // ---- phase 2b: 17 selected prob dots per pixel (16 lanes/pixel) ----
    float ssp = 0.f, ssn = 0.f, cnt = 0.f;
    if (act) {
        if (lane == 0) cnt = 1.f;
        const float4* A = reinterpret_cast<const float4*>(g_pp + (size_t)pix * NCP);
        #pragma unroll 1
        for (int tid = lane; tid < NTOP + NBOT; tid += 16) {
            unsigned long long kk = sel[g][tid];
            bool isTop = tid < NTOP;
            int k = isTop ? (63 - (int)(kk & 63u)) : (int)(kk & 63u);
            float val = f_of_ord((unsigned)(kk >> 8));
            int dy = ((k * 9363) >> 16) - 3;
            int dx = k - (dy + 3) * KK - 3;
            int hn = h + dy, wn = w + dx;
            float cp = 1.f / 19.f;
            if ((unsigned)hn < (unsigned)HH && (unsigned)wn < (unsigned)WW) {
                const float4* Bv = reinterpret_cast<const float4*>(
                    g_pp + (size_t)(pix + dy * WW + dx) * NCP);
                float d2 = 0.f;
                #pragma unroll
                for (int i = 0; i < 5; i++) d2 += dot4(A[i], Bv[i]);
                cp = d2;
            }
            if (isTop) ssp = fmaf(val, -cp, ssp);
            else       ssn += (1.f - val) * (-(1.f - cp));
        }
    }
    #pragma unroll
    for (int o = 16; o; o >>= 1) {
        ssp += __shfl_xor_sync(0xffffffffu, ssp, o);
        ssn += __shfl_xor_sync(0xffffffffu, ssn, o);
        cnt += __shfl_xor_sync(0xffffffffu, cnt, o);
    }
    if ((threadIdx.x & 31) == 0) {
        atomicAdd(&sred[0], ssp);
        atomicAdd(&sred[1], ssn);
        atomicAdd(&sred[2], cnt);
    }
    __syncthreads();
    if (threadIdx.x == 0) {
        atomicAdd(&g_acc[4], (double)sred[0]);
        atomicAdd(&g_acc[5], (double)sred[1]);
        atomicAdd(&g_acc[6], (double)sred[2]);
    }
}

__global__ void k_final(float* __restrict__ out) {
    if (threadIdx.x != 0) return;
    double cntP = g_acc[1];
    double cntN = 49.0 * g_acc[3] - cntP;
    double src_pos = g_acc[0] / fmax(cntP, 1.0);
    double src_neg = g_acc[2] / fmax(cntN, 1.0);
    double sim_pos = g_acc[4] / fmax((double)NTOP * g_acc[6], 1.0);
    double sim_neg = g_acc[5] / fmax((double)NBOT * g_acc[6], 1.0);
    out[0] = (float)(-src_pos);
    out[1] = (float)( src_neg);
    out[2] = (float)( sim_pos);
    out[3] = (float)( sim_neg);
}

extern "C" void kernel_launch(void* const* d_in, const int* in_sizes, int n_in,
                              void* d_out, int out_size) {
    (void)in_sizes; (void)n_in; (void)out_size;
    const float* logits = (const float*)d_in[0];
    const int*   gt     = (const int*)d_in[1];
    const float* xe     = (const float*)d_in[2];
    const float* xs     = (const float*)d_in[3];
    const float* mix    = (const float*)d_in[4];
    float* out = (float*)d_out;

    k_prep<<<2 * NT + NPIX / 256, 256>>>(xs, xe, logits);
    k_src<<<1024, 512>>>(gt);
    k_trg<<<2048, 256>>>(mix);
    k_final<<<1, 32>>>(out);
}

// round 8
// speedup vs baseline: 1.2998x; 1.0778x over previous
#include <cuda_runtime.h>
#include <math.h>

// ---------------------------------------------------------------------------
// LocalPseudoFeatLoss: B=2, C=19, H=W=128, CH=64, K=7, TOPK=8
// ---------------------------------------------------------------------------

namespace {
constexpr int NC   = 19;
constexpr int NCP  = 20;     // padded classes
constexpr int HH   = 128;
constexpr int WW   = 128;
constexpr int HWp  = HH * WW;
constexpr int FC   = 64;
constexpr int KK   = 7;
constexpr int K2   = KK * KK;
constexpr int NTOP = 9;
constexpr int NBOT = 8;
constexpr int NPIX = 2 * HWp;
constexpr float EPSV = 1e-8f;
constexpr int FB = FC * 4;    // feature row bytes
constexpr int PB = NCP * 4;   // prob row bytes
constexpr int NT = NPIX / 32; // transpose blocks per tensor (1024)
constexpr int SRC_BLOCKS = 2048;
constexpr int TRG_BLOCKS = 2048;
constexpr int MAIN_BLOCKS = SRC_BLOCKS + TRG_BLOCKS;
}

__device__ float  g_xs[NPIX * FC];     // normalized x_src, pixel-major
__device__ float  g_xe[NPIX * FC];     // normalized x_ema, pixel-major
__device__ float  g_pp[NPIX * NCP];    // softmax(logits), pixel-major, padded
__device__ double g_acc[8];
__device__ int    g_done;
// 0 sum_src_pos  1 cnt_src_pos  2 sum_src_neg  3 n_valid_src
// 4 sum_sim_pos  5 sum_sim_neg  6 cnt_trg

__device__ __forceinline__ float dot4(float4 a, float4 b) {
    float d = a.x * b.x;
    d = fmaf(a.y, b.y, d);
    d = fmaf(a.z, b.z, d);
    d = fmaf(a.w, b.w, d);
    return d;
}

__device__ __forceinline__ unsigned ord_of_f(float f) {
    unsigned b = __float_as_uint(f);
    return b ^ (((unsigned)((int)b >> 31)) | 0x80000000u);
}
__device__ __forceinline__ float f_of_ord(unsigned u) {
    unsigned b = (u & 0x80000000u) ? (u ^ 0x80000000u) : ~u;
    return __uint_as_float(b);
}

// Reduce 8 values across 16 lanes; lanes {2n,2n+1} hold total of value n.
__device__ __forceinline__ float tree8(float v[8], unsigned mask, int lane) {
    {   bool hi = (lane & 8) != 0;
        #pragma unroll
        for (int j = 0; j < 4; j++) {
            float mine = hi ? v[j] : v[j + 4];
            float kept = hi ? v[j + 4] : v[j];
            v[j] = kept + __shfl_xor_sync(mask, mine, 8);
        } }
    {   bool hi = (lane & 4) != 0;
        #pragma unroll
        for (int j = 0; j < 2; j++) {
            float mine = hi ? v[j] : v[j + 2];
            float kept = hi ? v[j + 2] : v[j];
            v[j] = kept + __shfl_xor_sync(mask, mine, 4);
        } }
    {   bool hi = (lane & 2) != 0;
        float mine = hi ? v[0] : v[1];
        float kept = hi ? v[1] : v[0];
        v[0] = kept + __shfl_xor_sync(mask, mine, 2);
    }
    v[0] += __shfl_xor_sync(mask, v[0], 1);
    return v[0];
}

// ---- fused prep: blocks [0,NT) transpose xs, [NT,2NT) xe, rest softmax ----
__device__ __forceinline__ void transpose_block(const float* __restrict__ src,
                                                float* __restrict__ dst,
                                                int blk, int t) {
    __shared__ float sm[FC][33];
    int pix0 = blk * 32;
    int b   = pix0 / HWp;
    int hw0 = pix0 - b * HWp;

    int px = t & 31, cb = (t >> 5) * 8;
    const float* sp = src + (size_t)b * FC * HWp + hw0 + px;
    #pragma unroll
    for (int j = 0; j < 8; j++)
        sm[cb + j][px] = sp[(size_t)(cb + j) * HWp];
    __syncthreads();

    int px2 = t >> 3, part = t & 7;
    float v[8];
    float ss = 0.f;
    #pragma unroll
    for (int j = 0; j < 8; j++) {
        v[j] = sm[part * 8 + j][px2];
        ss = fmaf(v[j], v[j], ss);
    }
    #pragma unroll
    for (int o = 4; o; o >>= 1) ss += __shfl_xor_sync(0xffffffffu, ss, o);
    float rn = 1.f / fmaxf(sqrtf(ss), EPSV);
    float4* d = reinterpret_cast<float4*>(dst + (size_t)(pix0 + px2) * FC + part * 8);
    d[0] = make_float4(v[0] * rn, v[1] * rn, v[2] * rn, v[3] * rn);
    d[1] = make_float4(v[4] * rn, v[5] * rn, v[6] * rn, v[7] * rn);
}

__global__ void __launch_bounds__(256)
k_prep(const float* __restrict__ xs, const float* __restrict__ xe,
       const float* __restrict__ logits) {
    int bx = blockIdx.x;
    int t = threadIdx.x;
    if (bx < NT) {
        transpose_block(xs, g_xs, bx, t);
    } else if (bx < 2 * NT) {
        transpose_block(xe, g_xe, bx - NT, t);
    } else {
        int sb = bx - 2 * NT;
        if (sb == 0 && t < 8) g_acc[t] = 0.0;
        if (sb == 0 && t == 8) g_done = 0;
        int pix = sb * 256 + t;
        if (pix >= NPIX) return;
        int b  = pix / HWp;
        int hw = pix - b * HWp;
        const float* lb = logits + (size_t)b * NC * HWp + hw;
        float l[NC];
        float mx = -3.4e38f;
        #pragma unroll
        for (int c = 0; c < NC; c++) {
            l[c] = lb[(size_t)c * HWp];
            mx = fmaxf(mx, l[c]);
        }
        float s = 0.f;
        #pragma unroll
        for (int c = 0; c < NC; c++) { l[c] = expf(l[c] - mx); s += l[c]; }
        float inv = 1.f / s;
        #pragma unroll
        for (int c = 0; c < NC; c++) g_pp[(size_t)pix * NCP + c] = l[c] * inv;
        g_pp[(size_t)pix * NCP + NC] = 0.f;
    }
}

// ---- src path: pair-symmetric, 24 forward neighbors + analytic center ----
__device__ __forceinline__ void src_path(const int* __restrict__ gt, int bx) {
    int b  = bx >> 10;
    int tt = bx & 1023;               // 32x32 tiles of 4x4
    int h0 = (tt >> 5) << 2;
    int w0 = (tt & 31) << 2;
    int g    = threadIdx.x >> 4;
    int lane = threadIdx.x & 15;
    unsigned gmask = 0xFFFFu << (threadIdx.x & 16);
    int h = h0 + (g >> 2), w = w0 + (g & 3);
    int pix = b * HWp + h * WW + w;

    bool interior = (h0 >= 4) && (h0 <= 120) && (w0 >= 4) && (w0 <= 120);

    int gc = gt[pix];
    float wp = (gc != 255) ? 1.f : 0.f;

    float sp = 0.f, sn = 0.f, cp = 0.f, nv = 0.f;

    const char* Pl = (const char*)g_xs + (size_t)pix * FB + lane * 16;
    float4 f = *(const float4*)Pl;
    const int* Pg = gt + pix;

    if (interior) {
        #pragma unroll
        for (int c = 0; c < 3; c++) {
            #pragma unroll
            for (int n = 0; n < 8; n++) {
                int k  = 25 + c * 8 + n;         // compile-time
                int dy = k / KK - 3;
                int dx = k - (k / KK) * KK - 3;
                int off = dy * WW + dx;
                float4 nf = *(const float4*)(Pl + (ptrdiff_t)off * FB);
                float s = dot4(f, nf);
                int gq = Pg[off];
                float wgt = wp + ((gq != 255) ? 1.f : 0.f);
                if (gq == gc) sp = fmaf(wgt, s, sp);
                else          sn = fmaf(wgt, s, sn);
            }
        }
    } else {
        #pragma unroll 1
        for (int k = 25; k < K2; k++) {
            int dy = k / KK - 3;
            int dx = k - (k / KK) * KK - 3;
            int hn = h + dy, wn = w + dx;
            if ((unsigned)hn < (unsigned)HH && (unsigned)wn < (unsigned)WW) {
                int off = dy * WW + dx;
                float4 nf = *(const float4*)(Pl + (ptrdiff_t)off * FB);
                float s = dot4(f, nf);
                int gq = Pg[off];
                float wgt = wp + ((gq != 255) ? 1.f : 0.f);
                if (gq == gc) sp = fmaf(wgt, s, sp);
                else          sn = fmaf(wgt, s, sn);
            }
        }
    }
    if (lane == 0) {
        sp += wp;        // center pair (k=24): sim = 1, pos
        nv  = wp;
    }

    if (gc != 255) {
        if (interior) {
            #pragma unroll 1
            for (int k = lane; k < K2; k += 16) {
                int dy = ((k * 9363) >> 16) - 3;       // k/7 - 3
                int dx = k - (dy + 3) * KK - 3;
                if (Pg[dy * WW + dx] == gc) cp += 1.f;
            }
        } else {
            #pragma unroll 1
            for (int k = lane; k < K2; k += 16) {
                int dy = ((k * 9363) >> 16) - 3;
                int dx = k - (dy + 3) * KK - 3;
                int hn = h + dy, wn = w + dx;
                int gn = 0;
                if ((unsigned)hn < (unsigned)HH && (unsigned)wn < (unsigned)WW)
                    gn = Pg[dy * WW + dx];
                if (gn == gc) cp += 1.f;
            }
        }
    }

    #pragma unroll
    for (int o = 8; o; o >>= 1) {
        sp += __shfl_xor_sync(gmask, sp, o);
        sn += __shfl_xor_sync(gmask, sn, o);
        cp += __shfl_xor_sync(gmask, cp, o);
        nv += __shfl_xor_sync(gmask, nv, o);
    }
    __shared__ float sa[4];
    if (threadIdx.x < 4) sa[threadIdx.x] = 0.f;
    __syncthreads();
    if (lane == 0) {
        atomicAdd(&sa[0], sp);
        atomicAdd(&sa[1], cp);
        atomicAdd(&sa[2], sn);
        atomicAdd(&sa[3], nv);
    }
    __syncthreads();
    if (threadIdx.x == 0) {
        atomicAdd(&g_acc[0], (double)sa[0]);
        atomicAdd(&g_acc[1], (double)sa[1]);
        atomicAdd(&g_acc[2], (double)sa[2]);
        atomicAdd(&g_acc[3], (double)sa[3]);
    }
}

// ---- trg path: sims -> packed-key top-k -> selected cross-probs ----
__device__ __forceinline__ void trg_path(const float* __restrict__ mix, int bx) {
    __shared__ float sm_s[K2][17];
    __shared__ unsigned long long sel[16][18];
    __shared__ float sred[3];

    int b  = bx >> 10;
    int tt = bx & 1023;               // 32x32 tiles of 4x4
    int h0 = (tt >> 5) << 2;
    int w0 = (tt & 31) << 2;
    int g    = threadIdx.x >> 4;      // 0..15 pixel in tile
    int lane = threadIdx.x & 15;
    unsigned gmask = 0xFFFFu << (threadIdx.x & 16);
    int h = h0 + (g >> 2), w = w0 + (g & 3);
    int pix = b * HWp + h * WW + w;

    bool interior = (h0 >= 4) && (h0 <= 120) && (w0 >= 4) && (w0 <= 120);
    bool act = (1.f - mix[pix]) > 0.5f;

    if (act) {
        const char* Pl = (const char*)g_xe + (size_t)pix * FB + lane * 16;
        float4 f = *(const float4*)Pl;
        if (interior) {
            #pragma unroll
            for (int c = 0; c < 6; c++) {
                float sv[8];
                #pragma unroll
                for (int n = 0; n < 8; n++) {
                    int k  = c * 8 + n;
                    int dy = k / KK - 3;
                    int dx = k - (k / KK) * KK - 3;
                    int off = dy * WW + dx;
                    float4 nf = *(const float4*)(Pl + (ptrdiff_t)off * FB);
                    sv[n] = dot4(f, nf);
                }
                float s0 = tree8(sv, gmask, lane);
                if (!(lane & 1)) sm_s[c * 8 + (lane >> 1)][g] = s0;
            }
            {   // straggler k = 48
                float4 nf = *(const float4*)(Pl + (ptrdiff_t)(3 * WW + 3) * FB);
                float pd = dot4(f, nf);
                #pragma unroll
                for (int o = 8; o; o >>= 1)
                    pd += __shfl_xor_sync(gmask, pd, o);
                if (lane == 0) sm_s[48][g] = pd;
            }
        } else {
            int k = 0;
            #pragma unroll 1
            for (int ky = 0; ky < KK; ky++) {
                int hn = h + ky - 3;
                bool rv = (unsigned)hn < (unsigned)HH;
                int hc = min(max(hn, 0), HH - 1);
                #pragma unroll
                for (int kx = 0; kx < KK; kx++, k++) {
                    int wn = w + kx - 3;
                    bool ok = rv && ((unsigned)wn < (unsigned)WW);
                    int wc = min(max(wn, 0), WW - 1);
                    int pn = b * HWp + hc * WW + wc;
                    float4 nf = *(const float4*)((const char*)g_xe + (size_t)pn * FB + lane * 16);
                    float pd = dot4(f, nf);
                    #pragma unroll
                    for (int o = 8; o; o >>= 1)
                        pd += __shfl_xor_sync(gmask, pd, o);
                    if (lane == 0) sm_s[k][g] = ok ? pd : 0.f;
                }
            }
        }
    }
    if (threadIdx.x < 3) sred[threadIdx.x] = 0.f;
    __syncthreads();

    // phase 2a: selection on packed keys (32 threads)
    if (threadIdx.x < 32) {
        int t = threadIdx.x;
        int q2 = t & 15;
        int h2 = h0 + (q2 >> 2), w2 = w0 + (q2 & 3);
        int p2 = b * HWp + h2 * WW + w2;
        if ((1.f - mix[p2]) > 0.5f) {
            if (t < 16) {
                unsigned long long key[NTOP];
                #pragma unroll
                for (int i = 0; i < NTOP; i++) key[i] = 0ull;
                #pragma unroll 1
                for (int k = 0; k < K2; k++) {
                    unsigned long long kk =
                        ((unsigned long long)ord_of_f(sm_s[k][q2]) << 8)
                        | (unsigned)(63 - k);
                    if (kk > key[NTOP - 1]) {
                        #pragma unroll
                        for (int i = 0; i < NTOP; i++)
                            if (kk > key[i]) {
                                unsigned long long x = key[i]; key[i] = kk; kk = x;
                            }
                    }
                }
                #pragma unroll
                for (int i = 0; i < NTOP; i++) sel[q2][i] = key[i];
            } else {
                unsigned long long key[NBOT];
                #pragma unroll
                for (int i = 0; i < NBOT; i++) key[i] = ~0ull;
                #pragma unroll 1
                for (int k = 0; k < K2; k++) {
                    unsigned long long kk =
                        ((unsigned long long)ord_of_f(sm_s[k][q2]) << 8)
                        | (unsigned)k;
                    if (kk < key[NBOT - 1]) {
                        #pragma unroll
                        for (int i = 0; i < NBOT; i++)
                            if (kk < key[i]) {
                                unsigned long long x = key[i]; key[i] = kk; kk = x;
                            }
                    }
                }
                #pragma unroll
                for (int i = 0; i < NBOT; i++) sel[q2][NTOP + i] = key[i];
            }
        }
    }
    __syncthreads();

    // phase 2b: 17 selected prob dots per pixel (16 lanes/pixel)
    float ssp = 0.f, ssn = 0.f, cnt = 0.f;
    if (act) {
        if (lane == 0) cnt = 1.f;
        const float4* A = reinterpret_cast<const float4*>(g_pp + (size_t)pix * NCP);
        #pragma unroll 1
        for (int tid = lane; tid < NTOP + NBOT; tid += 16) {
            unsigned long long kk = sel[g][tid];
            bool isTop = tid < NTOP;
            int k = isTop ? (63 - (int)(kk & 63u)) : (int)(kk & 63u);
            float val = f_of_ord((unsigned)(kk >> 8));
            int dy = ((k * 9363) >> 16) - 3;
            int dx = k - (dy + 3) * KK - 3;
            int hn = h + dy, wn = w + dx;
            float cp = 1.f / 19.f;
            if ((unsigned)hn < (unsigned)HH && (unsigned)wn < (unsigned)WW) {
                const float4* Bv = reinterpret_cast<const float4*>(
                    g_pp + (size_t)(pix + dy * WW + dx) * NCP);
                float d2 = 0.f;
                #pragma unroll
                for (int i = 0; i < 5; i++) d2 += dot4(A[i], Bv[i]);
                cp = d2;
            }
            if (isTop) ssp = fmaf(val, -cp, ssp);
            else       ssn += (1.f - val) * (-(1.f - cp));
        }
    }
    #pragma unroll
    for (int o = 16; o; o >>= 1) {
        ssp += __shfl_xor_sync(0xffffffffu, ssp, o);
        ssn += __shfl_xor_sync(0xffffffffu, ssn, o);
        cnt += __shfl_xor_sync(0xffffffffu, cnt, o);
    }
    if ((threadIdx.x & 31) == 0) {
        atomicAdd(&sred[0], ssp);
        atomicAdd(&sred[1], ssn);
        atomicAdd(&sred[2], cnt);
    }
    __syncthreads();
    if (threadIdx.x == 0) {
        atomicAdd(&g_acc[4], (double)sred[0]);
        atomicAdd(&g_acc[5], (double)sred[1]);
        atomicAdd(&g_acc[6], (double)sred[2]);
    }
}

// ---- merged main kernel: src blocks + trg blocks + last-block finalize ----
__global__ void __launch_bounds__(256)
k_main(const int* __restrict__ gt, const float* __restrict__ mix,
       float* __restrict__ out) {
    int bx = blockIdx.x;
    if (bx < SRC_BLOCKS) src_path(gt, bx);
    else                 trg_path(mix, bx - SRC_BLOCKS);

    // last finishing block computes the final 4 outputs
    __shared__ bool isLast;
    if (threadIdx.x == 0) {
        __threadfence();
        int prev = atomicAdd(&g_done, 1);
        isLast = (prev == MAIN_BLOCKS - 1);
    }
    __syncthreads();
    if (isLast && threadIdx.x == 0) {
        double cntP = g_acc[1];
        double cntN = 49.0 * g_acc[3] - cntP;
        double src_pos = g_acc[0] / fmax(cntP, 1.0);
        double src_neg = g_acc[2] / fmax(cntN, 1.0);
        double sim_pos = g_acc[4] / fmax((double)NTOP * g_acc[6], 1.0);
        double sim_neg = g_acc[5] / fmax((double)NBOT * g_acc[6], 1.0);
        out[0] = (float)(-src_pos);
        out[1] = (float)( src_neg);
        out[2] = (float)( sim_pos);
        out[3] = (float)( sim_neg);
    }
}

extern "C" void kernel_launch(void* const* d_in, const int* in_sizes, int n_in,
                              void* d_out, int out_size) {
    (void)in_sizes; (void)n_in; (void)out_size;
    const float* logits = (const float*)d_in[0];
    const int*   gt     = (const int*)d_in[1];
    const float* xe     = (const float*)d_in[2];
    const float* xs     = (const float*)d_in[3];
    const float* mix    = (const float*)d_in[4];
    float* out = (float*)d_out;

    k_prep<<<2 * NT + NPIX / 256, 256>>>(xs, xe, logits);
    k_main<<<MAIN_BLOCKS, 256>>>(gt, mix, out);
}

// round 9
// speedup vs baseline: 1.6171x; 1.2442x over previous
#include <cuda_runtime.h>
#include <math.h>

// ---------------------------------------------------------------------------
// LocalPseudoFeatLoss: B=2, C=19, H=W=128, CH=64, K=7, TOPK=8
// 8 lanes x 8 channels per pixel; 32 px per 256-thread block.
// ---------------------------------------------------------------------------

namespace {
constexpr int NC   = 19;
constexpr int NCP  = 20;     // padded classes
constexpr int HH   = 128;
constexpr int WW   = 128;
constexpr int HWp  = HH * WW;
constexpr int FC   = 64;
constexpr int KK   = 7;
constexpr int K2   = KK * KK;
constexpr int NTOP = 9;
constexpr int NBOT = 8;
constexpr int NPIX = 2 * HWp;
constexpr float EPSV = 1e-8f;
constexpr int FB = FC * 4;    // feature row bytes
constexpr int PB = NCP * 4;   // prob row bytes
constexpr int NT = NPIX / 32; // transpose blocks per tensor (1024)
constexpr int SRC_BLOCKS = 1024;
constexpr int TRG_BLOCKS = 1024;
constexpr int MAIN_BLOCKS = SRC_BLOCKS + TRG_BLOCKS;
}

__device__ float  g_xs[NPIX * FC];     // normalized x_src, pixel-major
__device__ float  g_xe[NPIX * FC];     // normalized x_ema, pixel-major
__device__ float  g_pp[NPIX * NCP];    // softmax(logits), pixel-major, padded
__device__ double g_acc[8];
__device__ int    g_done;
// 0 sum_src_pos  1 cnt_src_pos  2 sum_src_neg  3 n_valid_src
// 4 sum_sim_pos  5 sum_sim_neg  6 cnt_trg

__device__ __forceinline__ float dot4(float4 a, float4 b) {
    float d = a.x * b.x;
    d = fmaf(a.y, b.y, d);
    d = fmaf(a.z, b.z, d);
    d = fmaf(a.w, b.w, d);
    return d;
}

__device__ __forceinline__ unsigned ord_of_f(float f) {
    unsigned b = __float_as_uint(f);
    return b ^ (((unsigned)((int)b >> 31)) | 0x80000000u);
}
__device__ __forceinline__ float f_of_ord(unsigned u) {
    unsigned b = (u & 0x80000000u) ? (u ^ 0x80000000u) : ~u;
    return __uint_as_float(b);
}

// Reduce 8 values across 8 lanes (3 exchange stages).
// On return, lane n of the 8-lane segment holds the total of value n (in v[0]).
__device__ __forceinline__ void tree8x8(float v[8], unsigned mask, int lane) {
    {   bool hi = (lane & 4) != 0;
        #pragma unroll
        for (int j = 0; j < 4; j++) {
            float mine = hi ? v[j] : v[j + 4];
            float kept = hi ? v[j + 4] : v[j];
            v[j] = kept + __shfl_xor_sync(mask, mine, 4);
        } }
    {   bool hi = (lane & 2) != 0;
        #pragma unroll
        for (int j = 0; j < 2; j++) {
            float mine = hi ? v[j] : v[j + 2];
            float kept = hi ? v[j + 2] : v[j];
            v[j] = kept + __shfl_xor_sync(mask, mine, 2);
        } }
    {   bool hi = (lane & 1) != 0;
        float mine = hi ? v[0] : v[1];
        float kept = hi ? v[1] : v[0];
        v[0] = kept + __shfl_xor_sync(mask, mine, 1);
    }
}

// ---- fused prep: blocks [0,NT) transpose xs, [NT,2NT) xe, rest softmax ----
__device__ __forceinline__ void transpose_block(const float* __restrict__ src,
                                                float* __restrict__ dst,
                                                int blk, int t) {
    __shared__ float sm[FC][33];
    int pix0 = blk * 32;
    int b   = pix0 / HWp;
    int hw0 = pix0 - b * HWp;

    int px = t & 31, cb = (t >> 5) * 8;
    const float* sp = src + (size_t)b * FC * HWp + hw0 + px;
    #pragma unroll
    for (int j = 0; j < 8; j++)
        sm[cb + j][px] = sp[(size_t)(cb + j) * HWp];
    __syncthreads();

    int px2 = t >> 3, part = t & 7;
    float v[8];
    float ss = 0.f;
    #pragma unroll
    for (int j = 0; j < 8; j++) {
        v[j] = sm[part * 8 + j][px2];
        ss = fmaf(v[j], v[j], ss);
    }
    #pragma unroll
    for (int o = 4; o; o >>= 1) ss += __shfl_xor_sync(0xffffffffu, ss, o);
    float rn = 1.f / fmaxf(sqrtf(ss), EPSV);
    float4* d = reinterpret_cast<float4*>(dst + (size_t)(pix0 + px2) * FC + part * 8);
    d[0] = make_float4(v[0] * rn, v[1] * rn, v[2] * rn, v[3] * rn);
    d[1] = make_float4(v[4] * rn, v[5] * rn, v[6] * rn, v[7] * rn);
}

__global__ void __launch_bounds__(256)
k_prep(const float* __restrict__ xs, const float* __restrict__ xe,
       const float* __restrict__ logits) {
    int bx = blockIdx.x;
    int t = threadIdx.x;
    if (bx < NT) {
        transpose_block(xs, g_xs, bx, t);
    } else if (bx < 2 * NT) {
        transpose_block(xe, g_xe, bx - NT, t);
    } else {
        int sb = bx - 2 * NT;
        if (sb == 0 && t < 8) g_acc[t] = 0.0;
        if (sb == 0 && t == 8) g_done = 0;
        int pix = sb * 256 + t;
        if (pix >= NPIX) return;
        int b  = pix / HWp;
        int hw = pix - b * HWp;
        const float* lb = logits + (size_t)b * NC * HWp + hw;
        float l[NC];
        float mx = -3.4e38f;
        #pragma unroll
        for (int c = 0; c < NC; c++) {
            l[c] = lb[(size_t)c * HWp];
            mx = fmaxf(mx, l[c]);
        }
        float s = 0.f;
        #pragma unroll
        for (int c = 0; c < NC; c++) { l[c] = expf(l[c] - mx); s += l[c]; }
        float inv = 1.f / s;
        #pragma unroll
        for (int c = 0; c < NC; c++) g_pp[(size_t)pix * NCP + c] = l[c] * inv;
        g_pp[(size_t)pix * NCP + NC] = 0.f;
    }
}

// ---- src path: pair-symmetric, 24 forward neighbors + analytic center ----
__device__ __forceinline__ void src_path(const int* __restrict__ gt, int bx) {
    int b  = bx >> 9;
    int tt = bx & 511;                // 16x32 tiles of 8x4
    int h0 = (tt >> 5) << 3;
    int w0 = (tt & 31) << 2;
    int g    = threadIdx.x >> 3;      // 0..31 pixel in tile
    int lane = threadIdx.x & 7;
    unsigned gmask = 0xFFu << (threadIdx.x & 24);
    int h = h0 + (g >> 2), w = w0 + (g & 3);
    int pix = b * HWp + h * WW + w;

    bool interior = (h0 >= 8) && (h0 <= 112) && (w0 >= 4) && (w0 <= 120);

    int gc = gt[pix];
    float wp = (gc != 255) ? 1.f : 0.f;

    float sp = 0.f, sn = 0.f, cp = 0.f, nv = 0.f;

    const char* Pl = (const char*)g_xs + (size_t)pix * FB + lane * 32;
    float4 f0 = *(const float4*)Pl;
    float4 f1 = *(const float4*)(Pl + 16);
    const int* Pg = gt + pix;

    if (interior) {
        #pragma unroll
        for (int c = 0; c < 3; c++) {
            #pragma unroll
            for (int n = 0; n < 8; n++) {
                int k  = 25 + c * 8 + n;         // compile-time
                int dy = k / KK - 3;
                int dx = k - (k / KK) * KK - 3;
                int off = dy * WW + dx;
                float4 n0 = *(const float4*)(Pl + (ptrdiff_t)off * FB);
                float4 n1 = *(const float4*)(Pl + (ptrdiff_t)off * FB + 16);
                float s = dot4(f0, n0) + dot4(f1, n1);
                int gq = Pg[off];
                float wgt = wp + ((gq != 255) ? 1.f : 0.f);
                if (gq == gc) sp = fmaf(wgt, s, sp);
                else          sn = fmaf(wgt, s, sn);
            }
        }
    } else {
        #pragma unroll 1
        for (int k = 25; k < K2; k++) {
            int dy = k / KK - 3;
            int dx = k - (k / KK) * KK - 3;
            int hn = h + dy, wn = w + dx;
            if ((unsigned)hn < (unsigned)HH && (unsigned)wn < (unsigned)WW) {
                int off = dy * WW + dx;
                float4 n0 = *(const float4*)(Pl + (ptrdiff_t)off * FB);
                float4 n1 = *(const float4*)(Pl + (ptrdiff_t)off * FB + 16);
                float s = dot4(f0, n0) + dot4(f1, n1);
                int gq = Pg[off];
                float wgt = wp + ((gq != 255) ? 1.f : 0.f);
                if (gq == gc) sp = fmaf(wgt, s, sp);
                else          sn = fmaf(wgt, s, sn);
            }
        }
    }
    if (lane == 0) {
        sp += wp;        // center pair (k=24): sim = 1, pos
        nv  = wp;
    }

    if (gc != 255) {
        if (interior) {
            #pragma unroll 1
            for (int k = lane; k < K2; k += 8) {
                int dy = ((k * 9363) >> 16) - 3;       // k/7 - 3
                int dx = k - (dy + 3) * KK - 3;
                if (Pg[dy * WW + dx] == gc) cp += 1.f;
            }
        } else {
            #pragma unroll 1
            for (int k = lane; k < K2; k += 8) {
                int dy = ((k * 9363) >> 16) - 3;
                int dx = k - (dy + 3) * KK - 3;
                int hn = h + dy, wn = w + dx;
                int gn = 0;
                if ((unsigned)hn < (unsigned)HH && (unsigned)wn < (unsigned)WW)
                    gn = Pg[dy * WW + dx];
                if (gn == gc) cp += 1.f;
            }
        }
    }

    #pragma unroll
    for (int o = 4; o; o >>= 1) {
        sp += __shfl_xor_sync(gmask, sp, o);
        sn += __shfl_xor_sync(gmask, sn, o);
        cp += __shfl_xor_sync(gmask, cp, o);
        nv += __shfl_xor_sync(gmask, nv, o);
    }
    __shared__ float sa[4];
    if (threadIdx.x < 4) sa[threadIdx.x] = 0.f;
    __syncthreads();
    if (lane == 0) {
        atomicAdd(&sa[0], sp);
        atomicAdd(&sa[1], cp);
        atomicAdd(&sa[2], sn);
        atomicAdd(&sa[3], nv);
    }
    __syncthreads();
    if (threadIdx.x == 0) {
        atomicAdd(&g_acc[0], (double)sa[0]);
        atomicAdd(&g_acc[1], (double)sa[1]);
        atomicAdd(&g_acc[2], (double)sa[2]);
        atomicAdd(&g_acc[3], (double)sa[3]);
    }
}

// ---- trg path: sims -> packed-key top-k -> selected cross-probs ----
__device__ __forceinline__ void trg_path(const float* __restrict__ mix, int bx) {
    __shared__ float sm_s[K2][36];   // pad 36: conflict-free tree stores/reads
    __shared__ unsigned long long sel[32][18];
    __shared__ float sred[3];

    int b  = bx >> 9;
    int tt = bx & 511;                // 16x32 tiles of 8x4
    int h0 = (tt >> 5) << 3;
    int w0 = (tt & 31) << 2;
    int g    = threadIdx.x >> 3;      // 0..31 pixel in tile
    int lane = threadIdx.x & 7;
    unsigned gmask = 0xFFu << (threadIdx.x & 24);
    int h = h0 + (g >> 2), w = w0 + (g & 3);
    int pix = b * HWp + h * WW + w;

    bool interior = (h0 >= 8) && (h0 <= 112) && (w0 >= 4) && (w0 <= 120);
    bool act = (1.f - mix[pix]) > 0.5f;

    if (act) {
        const char* Pl = (const char*)g_xe + (size_t)pix * FB + lane * 32;
        float4 f0 = *(const float4*)Pl;
        float4 f1 = *(const float4*)(Pl + 16);
        if (interior) {
            #pragma unroll
            for (int c = 0; c < 6; c++) {
                float sv[8];
                #pragma unroll
                for (int n = 0; n < 8; n++) {
                    int k  = c * 8 + n;
                    int dy = k / KK - 3;
                    int dx = k - (k / KK) * KK - 3;
                    int off = dy * WW + dx;
                    float4 n0 = *(const float4*)(Pl + (ptrdiff_t)off * FB);
                    float4 n1 = *(const float4*)(Pl + (ptrdiff_t)off * FB + 16);
                    sv[n] = dot4(f0, n0) + dot4(f1, n1);
                }
                tree8x8(sv, gmask, lane);
                sm_s[c * 8 + lane][g] = sv[0];
            }
            {   // straggler k = 48
                float4 n0 = *(const float4*)(Pl + (ptrdiff_t)(3 * WW + 3) * FB);
                float4 n1 = *(const float4*)(Pl + (ptrdiff_t)(3 * WW + 3) * FB + 16);
                float pd = dot4(f0, n0) + dot4(f1, n1);
                #pragma unroll
                for (int o = 4; o; o >>= 1)
                    pd += __shfl_xor_sync(gmask, pd, o);
                if (lane == 0) sm_s[48][g] = pd;
            }
        } else {
            int k = 0;
            #pragma unroll 1
            for (int ky = 0; ky < KK; ky++) {
                int hn = h + ky - 3;
                bool rv = (unsigned)hn < (unsigned)HH;
                int hc = min(max(hn, 0), HH - 1);
                #pragma unroll
                for (int kx = 0; kx < KK; kx++, k++) {
                    int wn = w + kx - 3;
                    bool ok = rv && ((unsigned)wn < (unsigned)WW);
                    int wc = min(max(wn, 0), WW - 1);
                    int pn = b * HWp + hc * WW + wc;
                    const char* Pn = (const char*)g_xe + (size_t)pn * FB + lane * 32;
                    float4 n0 = *(const float4*)Pn;
                    float4 n1 = *(const float4*)(Pn + 16);
                    float pd = dot4(f0, n0) + dot4(f1, n1);
                    #pragma unroll
                    for (int o = 4; o; o >>= 1)
                        pd += __shfl_xor_sync(gmask, pd, o);
                    if (lane == 0) sm_s[k][g] = ok ? pd : 0.f;
                }
            }
        }
    }
    if (threadIdx.x < 3) sred[threadIdx.x] = 0.f;
    __syncthreads();

    // phase 2a: selection on packed keys (64 threads, 32 top + 32 bottom)
    if (threadIdx.x < 64) {
        int t = threadIdx.x;
        int q2 = t & 31;
        int h2 = h0 + (q2 >> 2), w2 = w0 + (q2 & 3);
        int p2 = b * HWp + h2 * WW + w2;
        if ((1.f - mix[p2]) > 0.5f) {
            if (t < 32) {
                unsigned long long key[NTOP];
                #pragma unroll
                for (int i = 0; i < NTOP; i++) key[i] = 0ull;
                #pragma unroll 1
                for (int k = 0; k < K2; k++) {
                    unsigned long long kk =
                        ((unsigned long long)ord_of_f(sm_s[k][q2]) << 8)
                        | (unsigned)(63 - k);
                    if (kk > key[NTOP - 1]) {
                        #pragma unroll
                        for (int i = 0; i < NTOP; i++)
                            if (kk > key[i]) {
                                unsigned long long x = key[i]; key[i] = kk; kk = x;
                            }
                    }
                }
                #pragma unroll
                for (int i = 0; i < NTOP; i++) sel[q2][i] = key[i];
            } else {
                unsigned long long key[NBOT];
                #pragma unroll
                for (int i = 0; i < NBOT; i++) key[i] = ~0ull;
                #pragma unroll 1
                for (int k = 0; k < K2; k++) {
                    unsigned long long kk =
                        ((unsigned long long)ord_of_f(sm_s[k][q2]) << 8)
                        | (unsigned)k;
                    if (kk < key[NBOT - 1]) {
                        #pragma unroll
                        for (int i = 0; i < NBOT; i++)
                            if (kk < key[i]) {
                                unsigned long long x = key[i]; key[i] = kk; kk = x;
                            }
                    }
                }
                #pragma unroll
                for (int i = 0; i < NBOT; i++) sel[q2][NTOP + i] = key[i];
            }
        }
    }
    __syncthreads();

    // phase 2b: 17 selected prob dots per pixel (8 lanes/pixel)
    float ssp = 0.f, ssn = 0.f, cnt = 0.f;
    if (act) {
        if (lane == 0) cnt = 1.f;
        const float4* A = reinterpret_cast<const float4*>(g_pp + (size_t)pix * NCP);
        float4 A0 = A[0], A1 = A[1], A2 = A[2], A3 = A[3], A4 = A[4];
        #pragma unroll 1
        for (int tid = lane; tid < NTOP + NBOT; tid += 8) {
            unsigned long long kk = sel[g][tid];
            bool isTop = tid < NTOP;
            int k = isTop ? (63 - (int)(kk & 63u)) : (int)(kk & 63u);
            float val = f_of_ord((unsigned)(kk >> 8));
            int dy = ((k * 9363) >> 16) - 3;
            int dx = k - (dy + 3) * KK - 3;
            int hn = h + dy, wn = w + dx;
            float cpv = 1.f / 19.f;
            if ((unsigned)hn < (unsigned)HH && (unsigned)wn < (unsigned)WW) {
                const float4* Bv = reinterpret_cast<const float4*>(
                    g_pp + (size_t)(pix + dy * WW + dx) * NCP);
                float d2 = dot4(A0, Bv[0]);
                d2 += dot4(A1, Bv[1]);
                d2 += dot4(A2, Bv[2]);
                d2 += dot4(A3, Bv[3]);
                d2 += dot4(A4, Bv[4]);
                cpv = d2;
            }
            if (isTop) ssp = fmaf(val, -cpv, ssp);
            else       ssn += (1.f - val) * (-(1.f - cpv));
        }
    }
    #pragma unroll
    for (int o = 16; o; o >>= 1) {
        ssp += __shfl_xor_sync(0xffffffffu, ssp, o);
        ssn += __shfl_xor_sync(0xffffffffu, ssn, o);
        cnt += __shfl_xor_sync(0xffffffffu, cnt, o);
    }
    if ((threadIdx.x & 31) == 0) {
        atomicAdd(&sred[0], ssp);
        atomicAdd(&sred[1], ssn);
        atomicAdd(&sred[2], cnt);
    }
    __syncthreads();
    if (threadIdx.x == 0) {
        atomicAdd(&g_acc[4], (double)sred[0]);
        atomicAdd(&g_acc[5], (double)sred[1]);
        atomicAdd(&g_acc[6], (double)sred[2]);
    }
}

// ---- merged main kernel: src blocks + trg blocks + last-block finalize ----
__global__ void __launch_bounds__(256)
k_main(const int* __restrict__ gt, const float* __restrict__ mix,
       float* __restrict__ out) {
    int bx = blockIdx.x;
    if (bx < SRC_BLOCKS) src_path(gt, bx);
    else                 trg_path(mix, bx - SRC_BLOCKS);

    __shared__ bool isLast;
    if (threadIdx.x == 0) {
        __threadfence();
        int prev = atomicAdd(&g_done, 1);
        isLast = (prev == MAIN_BLOCKS - 1);
    }
    __syncthreads();
    if (isLast && threadIdx.x == 0) {
        double cntP = g_acc[1];
        double cntN = 49.0 * g_acc[3] - cntP;
        double src_pos = g_acc[0] / fmax(cntP, 1.0);
        double src_neg = g_acc[2] / fmax(cntN, 1.0);
        double sim_pos = g_acc[4] / fmax((double)NTOP * g_acc[6], 1.0);
        double sim_neg = g_acc[5] / fmax((double)NBOT * g_acc[6], 1.0);
        out[0] = (float)(-src_pos);
        out[1] = (float)( src_neg);
        out[2] = (float)( sim_pos);
        out[3] = (float)( sim_neg);
    }
}

extern "C" void kernel_launch(void* const* d_in, const int* in_sizes, int n_in,
                              void* d_out, int out_size) {
    (void)in_sizes; (void)n_in; (void)out_size;
    const float* logits = (const float*)d_in[0];
    const int*   gt     = (const int*)d_in[1];
    const float* xe     = (const float*)d_in[2];
    const float* xs     = (const float*)d_in[3];
    const float* mix    = (const float*)d_in[4];
    float* out = (float*)d_out;

    k_prep<<<2 * NT + NPIX / 256, 256>>>(xs, xe, logits);
    k_main<<<MAIN_BLOCKS, 256>>>(gt, mix, out);
}